// round 13
// baseline (speedup 1.0000x reference)
#include <cuda_runtime.h>
#include <cuda_bf16.h>
#include <math.h>
#include <stdint.h>

#define Bz 64
#define Tz 512
#define INz 512
#define Hz 1024
#define G3z 3072
#define BTz 32768

__device__ __align__(16) float g_xg[(size_t)BTz * G3z];
__device__ __align__(16) __nv_bfloat16 g_xhi[(size_t)BTz * INz];
__device__ __align__(16) __nv_bfloat16 g_xlo[(size_t)BTz * INz];
__device__ __align__(16) __nv_bfloat16 g_whi[G3z * INz];
__device__ __align__(16) __nv_bfloat16 g_wlo[G3z * INz];
__device__ __align__(16) float g_bias[G3z];
__device__ __align__(16) __nv_bfloat16 g_hhi[2][Bz * Hz];
__device__ __align__(16) __nv_bfloat16 g_hlo[2][Bz * Hz];
__device__ unsigned g_bc1[8];
__device__ unsigned g_bc2;
__device__ unsigned g_bg;

// ---------------- helpers ----------------
__device__ __forceinline__ uint32_t s2u(const void* p) {
    uint32_t a;
    asm("{ .reg .u64 t; cvta.to.shared.u64 t, %1; cvt.u32.u64 %0, t; }" : "=r"(a) : "l"(p));
    return a;
}
#define SWZ(o) ((uint32_t)(o) ^ (((uint32_t)(o) >> 3) & 0x70u))

#define LDSM4(r, a) asm volatile("ldmatrix.sync.aligned.m8n8.x4.shared.b16 {%0,%1,%2,%3}, [%4];" \
    : "=r"((r)[0]), "=r"((r)[1]), "=r"((r)[2]), "=r"((r)[3]) : "r"(a))
#define LDSM2(r, a) asm volatile("ldmatrix.sync.aligned.m8n8.x2.shared.b16 {%0,%1}, [%2];" \
    : "=r"((r)[0]), "=r"((r)[1]) : "r"(a))
#define MMA(d, a, b) asm volatile( \
    "mma.sync.aligned.m16n8k16.row.col.f32.bf16.bf16.f32 " \
    "{%0,%1,%2,%3}, {%4,%5,%6,%7}, {%8,%9}, {%0,%1,%2,%3};" \
    : "+f"((d)[0]), "+f"((d)[1]), "+f"((d)[2]), "+f"((d)[3]) \
    : "r"((a)[0]), "r"((a)[1]), "r"((a)[2]), "r"((a)[3]), "r"((b)[0]), "r"((b)[1]))

#define CP16(s, g) asm volatile("cp.async.cg.shared.global [%0], [%1], 16;" :: "r"(s), "l"(g) : "memory")
#define CPCOMMIT() asm volatile("cp.async.commit_group;" ::: "memory")
#define CPWAIT0()  asm volatile("cp.async.wait_group 0;" ::: "memory")

__device__ __forceinline__ void cvt8(float4 v0, float4 v1, uint4& hi, uint4& lo) {
    float f[8] = {v0.x, v0.y, v0.z, v0.w, v1.x, v1.y, v1.z, v1.w};
    uint32_t h[4], l[4];
    #pragma unroll
    for (int i = 0; i < 4; i++) {
        __nv_bfloat16 a = __float2bfloat16(f[2*i]), b = __float2bfloat16(f[2*i+1]);
        __nv_bfloat16 al = __float2bfloat16(f[2*i] - __bfloat162float(a));
        __nv_bfloat16 bl = __float2bfloat16(f[2*i+1] - __bfloat162float(b));
        __nv_bfloat162 hp = __halves2bfloat162(a, b), lp = __halves2bfloat162(al, bl);
        h[i] = *reinterpret_cast<uint32_t*>(&hp);
        l[i] = *reinterpret_cast<uint32_t*>(&lp);
    }
    hi = make_uint4(h[0], h[1], h[2], h[3]);
    lo = make_uint4(l[0], l[1], l[2], l[3]);
}

// tree grid barrier: release-atomics carry ordering (no explicit gpu fence)
__device__ __forceinline__ void grid_sync_t(int t, int c) {
    __syncthreads();
    if (threadIdx.x == 0) {
        unsigned tgt = (unsigned)(t + 1);
        int g = c >> 4;
        unsigned prev;
        bool rel = false;
        asm volatile("atom.add.release.gpu.global.u32 %0, [%1], 1;"
                     : "=r"(prev) : "l"(&g_bc1[g]) : "memory");
        if (prev == (unsigned)(t * 16 + 15)) {
            asm volatile("atom.add.release.gpu.global.u32 %0, [%1], 1;"
                         : "=r"(prev) : "l"(&g_bc2) : "memory");
            if (prev == (unsigned)(t * 8 + 7)) {
                asm volatile("st.release.gpu.global.u32 [%0], %1;" :: "l"(&g_bg), "r"(tgt) : "memory");
                rel = true;
            }
        }
        if (!rel) {
            unsigned v;
            do {
                __nanosleep(32);
                asm volatile("ld.acquire.gpu.global.u32 %0, [%1];" : "=r"(v) : "l"(&g_bg));
            } while (v < tgt);
        }
    }
    __syncthreads();
}

// ---------------- one-time converts / init ----------------
__global__ void init_h() {
    int i = blockIdx.x * blockDim.x + threadIdx.x;
    if (i < Bz * Hz) {
        g_hhi[0][i] = __float2bfloat16(0.0f);
        g_hlo[0][i] = __float2bfloat16(0.0f);
    }
    if (i < 8) g_bc1[i] = 0u;
    if (i == 8) g_bc2 = 0u;
    if (i == 9) g_bg = 0u;
}

__global__ void cvt_x(const float* __restrict__ x) {
    size_t u = (size_t)blockIdx.x * 256 + threadIdx.x;
    if (u < (size_t)BTz * INz / 8) {
        float4 a = *(const float4*)(x + u * 8);
        float4 b = *(const float4*)(x + u * 8 + 4);
        uint4 hi, lo; cvt8(a, b, hi, lo);
        *(uint4*)(g_xhi + u * 8) = hi;
        *(uint4*)(g_xlo + u * 8) = lo;
    }
}

__global__ void cvt_w(const float* __restrict__ Wir, const float* __restrict__ Wii, const float* __restrict__ Win,
                      const float* __restrict__ bir, const float* __restrict__ bii, const float* __restrict__ bin) {
    int u = blockIdx.x * 256 + threadIdx.x;
    if (u < G3z * INz / 8) {
        int row = u >> 6, un = u & 63;
        int gate = row >> 10, r = row & 1023;
        const float* W = (gate == 0) ? Wir : (gate == 1) ? Wii : Win;
        const float* s = W + (size_t)r * INz + un * 8;
        float4 a = *(const float4*)s, b = *(const float4*)(s + 4);
        uint4 hi, lo; cvt8(a, b, hi, lo);
        *(uint4*)(g_whi + (size_t)u * 8) = hi;
        *(uint4*)(g_wlo + (size_t)u * 8) = lo;
    }
    if (u < G3z) {
        int gate = u >> 10;
        const float* bb = (gate == 0) ? bir : (gate == 1) ? bii : bin;
        g_bias[u] = bb[u & 1023];
    }
}

// ---------------- phase 1: xg = x @ Wi^T + b (cp.async double-buffered) ----------------
#define XBUF 49152
#define XSM  98304

__device__ __forceinline__ void xfill(uint32_t sb, uint32_t ab, int m0, int n0, int kc, int tid) {
    int k0 = kc * 64;
    #pragma unroll
    for (int i = 0; i < 4; i++) {
        int u = tid + i * 256;
        int row = u >> 3, un = u & 7;
        size_t g = (size_t)(m0 + row) * INz + k0 + un * 8;
        uint32_t d = SWZ(row * 128 + un * 16);
        CP16(sb + ab + d,         g_xhi + g);
        CP16(sb + ab + 16384 + d, g_xlo + g);
    }
    #pragma unroll
    for (int i = 0; i < 2; i++) {
        int u = tid + i * 256;
        int row = u >> 3, un = u & 7;
        size_t g = (size_t)(n0 + row) * INz + k0 + un * 8;
        uint32_t d = SWZ(row * 128 + un * 16);
        CP16(sb + ab + 32768 + d, g_whi + g);
        CP16(sb + ab + 40960 + d, g_wlo + g);
    }
}

__global__ __launch_bounds__(256, 2) void xproj(void) {
    extern __shared__ __align__(16) char sm[];
    uint32_t sb = s2u(sm);
    int tid = threadIdx.x, lane = tid & 31, wid = tid >> 5;
    int m0 = blockIdx.x * 128;
    int n0 = blockIdx.y * 64;
    int wm = wid >> 1, wn = wid & 1;

    float acc[2][4][4];
    #pragma unroll
    for (int i = 0; i < 2; i++)
        #pragma unroll
        for (int j = 0; j < 4; j++)
            #pragma unroll
            for (int k = 0; k < 4; k++) acc[i][j][k] = 0.0f;

    xfill(sb, 0, m0, n0, 0, tid);
    CPCOMMIT();

    for (int kc = 0; kc < 8; kc++) {
        CPWAIT0();
        __syncthreads();
        if (kc < 7) {
            xfill(sb, ((kc + 1) & 1) * XBUF, m0, n0, kc + 1, tid);
            CPCOMMIT();
        }
        uint32_t ab = (kc & 1) * XBUF;

        #pragma unroll
        for (int ks = 0; ks < 4; ks++) {
            uint32_t ah0[4], ah1[4], al0[4], al1[4], bh[8], bl[8];
            int arow = wm * 32 + (lane & 7) + (lane & 8);
            int aku  = ks * 2 + (lane >> 4);
            uint32_t o0 = SWZ(arow * 128 + aku * 16);
            uint32_t o1 = SWZ((arow + 16) * 128 + aku * 16);
            LDSM4(ah0, sb + ab + o0);          LDSM4(ah1, sb + ab + o1);
            LDSM4(al0, sb + ab + 16384 + o0);  LDSM4(al1, sb + ab + 16384 + o1);
            int brow = wn * 32 + (lane & 7) + ((lane >> 4) & 1) * 8;
            int bku  = ks * 2 + ((lane >> 3) & 1);
            uint32_t p0 = SWZ(brow * 128 + bku * 16);
            uint32_t p1 = SWZ((brow + 16) * 128 + bku * 16);
            LDSM4(bh,     sb + ab + 32768 + p0);  LDSM4(bh + 4, sb + ab + 32768 + p1);
            LDSM4(bl,     sb + ab + 40960 + p0);  LDSM4(bl + 4, sb + ab + 40960 + p1);
            #pragma unroll
            for (int nt = 0; nt < 4; nt++) {
                MMA(acc[0][nt], ah0, bh + nt * 2);
                MMA(acc[1][nt], ah1, bh + nt * 2);
                MMA(acc[0][nt], ah0, bl + nt * 2);
                MMA(acc[1][nt], ah1, bl + nt * 2);
                MMA(acc[0][nt], al0, bh + nt * 2);
                MMA(acc[1][nt], al1, bh + nt * 2);
            }
        }
    }

    #pragma unroll
    for (int mt = 0; mt < 2; mt++)
        #pragma unroll
        for (int nt = 0; nt < 4; nt++) {
            int m = m0 + wm * 32 + mt * 16 + (lane >> 2);
            int n = n0 + wn * 32 + nt * 8 + 2 * (lane & 3);
            float b0 = __ldg(g_bias + n), b1 = __ldg(g_bias + n + 1);
            *(float2*)(g_xg + (size_t)m * G3z + n)       = make_float2(acc[mt][nt][0] + b0, acc[mt][nt][1] + b1);
            *(float2*)(g_xg + (size_t)(m + 8) * G3z + n) = make_float2(acc[mt][nt][2] + b0, acc[mt][nt][3] + b1);
        }
}

// ---------------- phase 2: persistent recurrence (24-unit balanced MMA) ----------------
// smem: WH 0 (64K) | WL 65536 | A0H 131072 | A0L 147456 | A1H 163840 | A1L 180224
//       Sacc 196608 (2*64*25*4=12800) | hown 209408 (2048) | total 211456
#define NCTA 128
#define GSM  211456

__device__ __forceinline__ float sigf(float v)   { return __fdividef(1.0f, 1.0f + __expf(-v)); }
__device__ __forceinline__ float tanhf_(float v) { return 1.0f - __fdividef(2.0f, __expf(2.0f * v) + 1.0f); }

__device__ __forceinline__ void fill_h(uint32_t sb, uint32_t ab,
                                       const __nv_bfloat16* hhi, const __nv_bfloat16* hlo,
                                       int kc, int tid) {
    #pragma unroll
    for (int i = 0; i < 4; i++) {
        int u = tid + i * 256;
        int b = u >> 4, un = u & 15;
        size_t g = (size_t)b * Hz + kc * 128 + un * 8;
        uint32_t d = SWZ(((un >> 3) * 64 + b) * 128 + (un & 7) * 16);
        CP16(sb + ab + d,         hhi + g);
        CP16(sb + ab + 16384 + d, hlo + g);
    }
}

__global__ __launch_bounds__(256, 1) void gru(
    const float* __restrict__ Whr, const float* __restrict__ Whi, const float* __restrict__ Whn,
    float* __restrict__ out, int write_last)
{
    extern __shared__ __align__(16) char sm[];
    uint32_t sb = s2u(sm);
    float* Sacc = (float*)(sm + 196608);      // [2][64][25]
    float* hown = (float*)(sm + 209408);
    int tid = threadIdx.x, lane = tid & 31, wid = tid >> 5;
    int c = blockIdx.x;

    // per-warp work units: u = wid*3+i over 24 = (mt 0..3) x (wn 0..2) x (kh 0..1)
    int mtv[3], wnv[3], khv[3];
    #pragma unroll
    for (int i = 0; i < 3; i++) {
        int u = wid * 3 + i;
        khv[i] = u & 1;
        wnv[i] = (u >> 1) % 3;
        mtv[i] = u / 6;
    }

    // one-time resident W (32 n-rows: 24 real + 8 zero) x 1024 k, hi/lo
    #pragma unroll
    for (int i = 0; i < 16; i++) {
        int u = tid + i * 256;
        int n = u >> 7, un = u & 127;
        int k = un * 8;
        uint4 hi = make_uint4(0, 0, 0, 0), lo = hi;
        if (n < 24) {
            const float* W = (n < 8) ? Whr : (n < 16) ? Whi : Whn;
            const float* s = W + (size_t)(c * 8 + (n & 7)) * Hz + k;
            float4 a = *(const float4*)s, b = *(const float4*)(s + 4);
            cvt8(a, b, hi, lo);
        }
        uint32_t off = SWZ(((k >> 6) * 32 + n) * 128 + ((k >> 3) & 7) * 16);
        *(uint4*)(sm + off)         = hi;
        *(uint4*)(sm + 65536 + off) = lo;
    }
    if (tid < 64) {
        #pragma unroll
        for (int j = 0; j < 8; j++) hown[tid * 8 + j] = 0.0f;
    }
    __syncthreads();

    for (int t = 0; t < Tz; t++) {
        int par = t & 1, nxt = par ^ 1;
        const __nv_bfloat16* hhi = g_hhi[par];
        const __nv_bfloat16* hlo = g_hlo[par];

        fill_h(sb, 131072, hhi, hlo, 0, tid);
        CPCOMMIT();

        float xr[8], xi[8], xn[8];
        if (tid < 64) {
            const float* xgrow = g_xg + (size_t)(tid * Tz + t) * G3z + c * 8;
            *(float4*)(xr)     = *(const float4*)(xgrow);
            *(float4*)(xr + 4) = *(const float4*)(xgrow + 4);
            *(float4*)(xi)     = *(const float4*)(xgrow + 1024);
            *(float4*)(xi + 4) = *(const float4*)(xgrow + 1028);
            *(float4*)(xn)     = *(const float4*)(xgrow + 2048);
            *(float4*)(xn + 4) = *(const float4*)(xgrow + 2052);
        }

        float acc[3][4];
        #pragma unroll
        for (int i = 0; i < 3; i++)
            #pragma unroll
            for (int j = 0; j < 4; j++) acc[i][j] = 0.0f;

        for (int kc = 0; kc < 8; kc++) {
            CPWAIT0();
            __syncthreads();
            if (kc < 7)
                fill_h(sb, 131072 + ((kc + 1) & 1) * 32768, hhi, hlo, kc + 1, tid);
            CPCOMMIT();
            uint32_t ab = 131072 + (kc & 1) * 32768;

            #pragma unroll
            for (int i = 0; i < 3; i++) {
                #pragma unroll
                for (int ks = 0; ks < 4; ks++) {
                    uint32_t ah[4], al[4], bh[2], bl[2];
                    int kk  = khv[i] * 64 + ks * 16;
                    int akk = kk + (lane >> 4) * 8;
                    int arow = mtv[i] * 16 + (lane & 7) + (lane & 8);
                    uint32_t o = SWZ(((akk >> 6) * 64 + arow) * 128 + ((akk >> 3) & 7) * 16);
                    LDSM4(ah, sb + ab + o);
                    LDSM4(al, sb + ab + 16384 + o);
                    int bkk = kc * 128 + kk + ((lane >> 3) & 1) * 8;
                    int brow = wnv[i] * 8 + (lane & 7);
                    uint32_t ob = SWZ(((bkk >> 6) * 32 + brow) * 128 + ((bkk >> 3) & 7) * 16);
                    LDSM2(bh, sb + ob);
                    LDSM2(bl, sb + 65536 + ob);
                    MMA(acc[i], ah, bh);
                    MMA(acc[i], ah, bl);
                    MMA(acc[i], al, bh);
                }
            }
        }

        // store partial gate pre-activations (each slot written once)
        #pragma unroll
        for (int i = 0; i < 3; i++) {
            int row = mtv[i] * 16 + (lane >> 2);
            int col = wnv[i] * 8 + 2 * (lane & 3);
            float* S = Sacc + khv[i] * 1600;
            S[row * 25 + col]           = acc[i][0];
            S[row * 25 + col + 1]       = acc[i][1];
            S[(row + 8) * 25 + col]     = acc[i][2];
            S[(row + 8) * 25 + col + 1] = acc[i][3];
        }
        __syncthreads();

        if (tid < 64) {
            int b = tid;
            const float* S0 = Sacc + b * 25;
            const float* S1 = Sacc + 1600 + b * 25;
            float hn[8];
            #pragma unroll
            for (int j = 0; j < 8; j++) {
                float r  = sigf(xr[j] + S0[j] + S1[j]);
                float z  = sigf(xi[j] + S0[8 + j] + S1[8 + j]);
                float nn = tanhf_(xn[j] + r * (S0[16 + j] + S1[16 + j]));
                hn[j] = (1.0f - z) * nn + z * hown[b * 8 + j];
                hown[b * 8 + j] = hn[j];
            }
            float4 o0 = make_float4(hn[0], hn[1], hn[2], hn[3]);
            float4 o1 = make_float4(hn[4], hn[5], hn[6], hn[7]);
            float* orow = out + (size_t)(b * Tz + t) * Hz + c * 8;
            *(float4*)orow = o0;
            *(float4*)(orow + 4) = o1;
            if (write_last && t == Tz - 1) {
                float* lrow = out + (size_t)BTz * Hz + (size_t)b * Hz + c * 8;
                *(float4*)lrow = o0;
                *(float4*)(lrow + 4) = o1;
            }
            uint4 hi, lo;
            cvt8(o0, o1, hi, lo);
            __stcg((uint4*)(g_hhi[nxt] + (size_t)b * Hz + c * 8), hi);
            __stcg((uint4*)(g_hlo[nxt] + (size_t)b * Hz + c * 8), lo);
        }
        grid_sync_t(t, c);
    }
}

// ---------------- launch ----------------
extern "C" void kernel_launch(void* const* d_in, const int* in_sizes, int n_in,
                              void* d_out, int out_size) {
    const float* x   = (const float*)d_in[0];
    const float* Wir = (const float*)d_in[1];
    const float* Wii = (const float*)d_in[2];
    const float* Win = (const float*)d_in[3];
    const float* bir = (const float*)d_in[4];
    const float* bii = (const float*)d_in[5];
    const float* bin = (const float*)d_in[6];
    const float* Whr = (const float*)d_in[7];
    const float* Whi = (const float*)d_in[8];
    const float* Whn = (const float*)d_in[9];
    float* out = (float*)d_out;

    int write_last = (out_size >= BTz * Hz + Bz * Hz) ? 1 : 0;

    cudaFuncSetAttribute(xproj, cudaFuncAttributeMaxDynamicSharedMemorySize, XSM);
    cudaFuncSetAttribute(gru,   cudaFuncAttributeMaxDynamicSharedMemorySize, GSM);

    init_h<<<(Bz * Hz + 255) / 256, 256>>>();
    cvt_x<<<(int)(((size_t)BTz * INz / 8 + 255) / 256), 256>>>(x);
    cvt_w<<<(G3z * INz / 8 + 255) / 256, 256>>>(Wir, Wii, Win, bir, bii, bin);

    dim3 g1(BTz / 128, G3z / 64);
    xproj<<<g1, 256, XSM>>>();

    gru<<<NCTA, 256, GSM>>>(Whr, Whi, Whn, out, write_last);
}

// round 14
// speedup vs baseline: 1.2354x; 1.2354x over previous
#include <cuda_runtime.h>
#include <cuda_bf16.h>
#include <math.h>
#include <stdint.h>

#define Bz 64
#define Tz 512
#define INz 512
#define Hz 1024
#define G3z 3072
#define BTz 32768

__device__ __align__(16) float g_xg[(size_t)BTz * G3z];
__device__ __align__(16) __nv_bfloat16 g_xhi[(size_t)BTz * INz];
__device__ __align__(16) __nv_bfloat16 g_xlo[(size_t)BTz * INz];
__device__ __align__(16) __nv_bfloat16 g_whi[G3z * INz];
__device__ __align__(16) __nv_bfloat16 g_wlo[G3z * INz];
__device__ __align__(16) float g_bias[G3z];
__device__ __align__(16) __nv_bfloat16 g_hhi[2][Bz * Hz];
__device__ __align__(16) __nv_bfloat16 g_hlo[2][Bz * Hz];
__device__ unsigned g_bc1[8];
__device__ unsigned g_bc2;
__device__ unsigned g_bg;

// ---------------- helpers ----------------
__device__ __forceinline__ uint32_t s2u(const void* p) {
    uint32_t a;
    asm("{ .reg .u64 t; cvta.to.shared.u64 t, %1; cvt.u32.u64 %0, t; }" : "=r"(a) : "l"(p));
    return a;
}
#define SWZ(o) ((uint32_t)(o) ^ (((uint32_t)(o) >> 3) & 0x70u))

#define LDSM4(r, a) asm volatile("ldmatrix.sync.aligned.m8n8.x4.shared.b16 {%0,%1,%2,%3}, [%4];" \
    : "=r"((r)[0]), "=r"((r)[1]), "=r"((r)[2]), "=r"((r)[3]) : "r"(a))
#define LDSM2(r, a) asm volatile("ldmatrix.sync.aligned.m8n8.x2.shared.b16 {%0,%1}, [%2];" \
    : "=r"((r)[0]), "=r"((r)[1]) : "r"(a))
#define MMA(d, a, b) asm volatile( \
    "mma.sync.aligned.m16n8k16.row.col.f32.bf16.bf16.f32 " \
    "{%0,%1,%2,%3}, {%4,%5,%6,%7}, {%8,%9}, {%0,%1,%2,%3};" \
    : "+f"((d)[0]), "+f"((d)[1]), "+f"((d)[2]), "+f"((d)[3]) \
    : "r"((a)[0]), "r"((a)[1]), "r"((a)[2]), "r"((a)[3]), "r"((b)[0]), "r"((b)[1]))

#define CP16(s, g) asm volatile("cp.async.cg.shared.global [%0], [%1], 16;" :: "r"(s), "l"(g) : "memory")
#define CPCOMMIT() asm volatile("cp.async.commit_group;" ::: "memory")
#define CPWAIT0()  asm volatile("cp.async.wait_group 0;" ::: "memory")

__device__ __forceinline__ void cvt8(float4 v0, float4 v1, uint4& hi, uint4& lo) {
    float f[8] = {v0.x, v0.y, v0.z, v0.w, v1.x, v1.y, v1.z, v1.w};
    uint32_t h[4], l[4];
    #pragma unroll
    for (int i = 0; i < 4; i++) {
        __nv_bfloat16 a = __float2bfloat16(f[2*i]), b = __float2bfloat16(f[2*i+1]);
        __nv_bfloat16 al = __float2bfloat16(f[2*i] - __bfloat162float(a));
        __nv_bfloat16 bl = __float2bfloat16(f[2*i+1] - __bfloat162float(b));
        __nv_bfloat162 hp = __halves2bfloat162(a, b), lp = __halves2bfloat162(al, bl);
        h[i] = *reinterpret_cast<uint32_t*>(&hp);
        l[i] = *reinterpret_cast<uint32_t*>(&lp);
    }
    hi = make_uint4(h[0], h[1], h[2], h[3]);
    lo = make_uint4(l[0], l[1], l[2], l[3]);
}

// tree grid barrier (R10 proven form)
__device__ __forceinline__ void grid_sync_t(int t, int c) {
    __syncthreads();
    if (threadIdx.x == 0) {
        asm volatile("fence.acq_rel.gpu;" ::: "memory");
        unsigned tgt = (unsigned)(t + 1);
        int g = c >> 4;
        bool done = false;
        if (atomicAdd(&g_bc1[g], 1u) == (unsigned)(t * 16 + 15)) {
            if (atomicAdd(&g_bc2, 1u) == (unsigned)(t * 8 + 7)) {
                asm volatile("fence.acq_rel.gpu;" ::: "memory");
                asm volatile("st.release.gpu.global.u32 [%0], %1;" :: "l"(&g_bg), "r"(tgt) : "memory");
                done = true;
            }
        }
        if (!done) {
            unsigned v;
            do {
                __nanosleep(32);
                asm volatile("ld.acquire.gpu.global.u32 %0, [%1];" : "=r"(v) : "l"(&g_bg));
            } while (v < tgt);
        }
    }
    __syncthreads();
}

// ---------------- one-time converts / init ----------------
__global__ void init_h() {
    int i = blockIdx.x * blockDim.x + threadIdx.x;
    if (i < Bz * Hz) {
        g_hhi[0][i] = __float2bfloat16(0.0f);
        g_hlo[0][i] = __float2bfloat16(0.0f);
    }
    if (i < 8) g_bc1[i] = 0u;
    if (i == 8) g_bc2 = 0u;
    if (i == 9) g_bg = 0u;
}

__global__ void cvt_x(const float* __restrict__ x) {
    size_t u = (size_t)blockIdx.x * 256 + threadIdx.x;
    if (u < (size_t)BTz * INz / 8) {
        float4 a = *(const float4*)(x + u * 8);
        float4 b = *(const float4*)(x + u * 8 + 4);
        uint4 hi, lo; cvt8(a, b, hi, lo);
        *(uint4*)(g_xhi + u * 8) = hi;
        *(uint4*)(g_xlo + u * 8) = lo;
    }
}

__global__ void cvt_w(const float* __restrict__ Wir, const float* __restrict__ Wii, const float* __restrict__ Win,
                      const float* __restrict__ bir, const float* __restrict__ bii, const float* __restrict__ bin) {
    int u = blockIdx.x * 256 + threadIdx.x;
    if (u < G3z * INz / 8) {
        int row = u >> 6, un = u & 63;
        int gate = row >> 10, r = row & 1023;
        const float* W = (gate == 0) ? Wir : (gate == 1) ? Wii : Win;
        const float* s = W + (size_t)r * INz + un * 8;
        float4 a = *(const float4*)s, b = *(const float4*)(s + 4);
        uint4 hi, lo; cvt8(a, b, hi, lo);
        *(uint4*)(g_whi + (size_t)u * 8) = hi;
        *(uint4*)(g_wlo + (size_t)u * 8) = lo;
    }
    if (u < G3z) {
        int gate = u >> 10;
        const float* bb = (gate == 0) ? bir : (gate == 1) ? bii : bin;
        g_bias[u] = bb[u & 1023];
    }
}

// ---------------- phase 1: xg = x @ Wi^T + b (cp.async double-buffered) ----------------
#define XBUF 49152
#define XSM  98304

__device__ __forceinline__ void xfill(uint32_t sb, uint32_t ab, int m0, int n0, int kc, int tid) {
    int k0 = kc * 64;
    #pragma unroll
    for (int i = 0; i < 4; i++) {
        int u = tid + i * 256;
        int row = u >> 3, un = u & 7;
        size_t g = (size_t)(m0 + row) * INz + k0 + un * 8;
        uint32_t d = SWZ(row * 128 + un * 16);
        CP16(sb + ab + d,         g_xhi + g);
        CP16(sb + ab + 16384 + d, g_xlo + g);
    }
    #pragma unroll
    for (int i = 0; i < 2; i++) {
        int u = tid + i * 256;
        int row = u >> 3, un = u & 7;
        size_t g = (size_t)(n0 + row) * INz + k0 + un * 8;
        uint32_t d = SWZ(row * 128 + un * 16);
        CP16(sb + ab + 32768 + d, g_whi + g);
        CP16(sb + ab + 40960 + d, g_wlo + g);
    }
}

__global__ __launch_bounds__(256, 2) void xproj(void) {
    extern __shared__ __align__(16) char sm[];
    uint32_t sb = s2u(sm);
    int tid = threadIdx.x, lane = tid & 31, wid = tid >> 5;
    int m0 = blockIdx.x * 128;
    int n0 = blockIdx.y * 64;
    int wm = wid >> 1, wn = wid & 1;

    float acc[2][4][4];
    #pragma unroll
    for (int i = 0; i < 2; i++)
        #pragma unroll
        for (int j = 0; j < 4; j++)
            #pragma unroll
            for (int k = 0; k < 4; k++) acc[i][j][k] = 0.0f;

    xfill(sb, 0, m0, n0, 0, tid);
    CPCOMMIT();

    for (int kc = 0; kc < 8; kc++) {
        CPWAIT0();
        __syncthreads();
        if (kc < 7) {
            xfill(sb, ((kc + 1) & 1) * XBUF, m0, n0, kc + 1, tid);
            CPCOMMIT();
        }
        uint32_t ab = (kc & 1) * XBUF;

        #pragma unroll
        for (int ks = 0; ks < 4; ks++) {
            uint32_t ah0[4], ah1[4], al0[4], al1[4], bh[8], bl[8];
            int arow = wm * 32 + (lane & 7) + (lane & 8);
            int aku  = ks * 2 + (lane >> 4);
            uint32_t o0 = SWZ(arow * 128 + aku * 16);
            uint32_t o1 = SWZ((arow + 16) * 128 + aku * 16);
            LDSM4(ah0, sb + ab + o0);          LDSM4(ah1, sb + ab + o1);
            LDSM4(al0, sb + ab + 16384 + o0);  LDSM4(al1, sb + ab + 16384 + o1);
            int brow = wn * 32 + (lane & 7) + ((lane >> 4) & 1) * 8;
            int bku  = ks * 2 + ((lane >> 3) & 1);
            uint32_t p0 = SWZ(brow * 128 + bku * 16);
            uint32_t p1 = SWZ((brow + 16) * 128 + bku * 16);
            LDSM4(bh,     sb + ab + 32768 + p0);  LDSM4(bh + 4, sb + ab + 32768 + p1);
            LDSM4(bl,     sb + ab + 40960 + p0);  LDSM4(bl + 4, sb + ab + 40960 + p1);
            #pragma unroll
            for (int nt = 0; nt < 4; nt++) {
                MMA(acc[0][nt], ah0, bh + nt * 2);
                MMA(acc[1][nt], ah1, bh + nt * 2);
                MMA(acc[0][nt], ah0, bl + nt * 2);
                MMA(acc[1][nt], ah1, bl + nt * 2);
                MMA(acc[0][nt], al0, bh + nt * 2);
                MMA(acc[1][nt], al1, bh + nt * 2);
            }
        }
    }

    #pragma unroll
    for (int mt = 0; mt < 2; mt++)
        #pragma unroll
        for (int nt = 0; nt < 4; nt++) {
            int m = m0 + wm * 32 + mt * 16 + (lane >> 2);
            int n = n0 + wn * 32 + nt * 8 + 2 * (lane & 3);
            float b0 = __ldg(g_bias + n), b1 = __ldg(g_bias + n + 1);
            *(float2*)(g_xg + (size_t)m * G3z + n)       = make_float2(acc[mt][nt][0] + b0, acc[mt][nt][1] + b1);
            *(float2*)(g_xg + (size_t)(m + 8) * G3z + n) = make_float2(acc[mt][nt][2] + b0, acc[mt][nt][3] + b1);
        }
}

// ---------------- phase 2: persistent recurrence (M4 x K2 balanced, A-reuse) ----------------
// smem: WH 0 (64K) | WL 65536 | A0H 131072 | A0L 147456 | A1H 163840 | A1L 180224
//       Sacc 196608 (2*64*25*4=12800) | hown 209408 (2048) | total 211456
#define NCTA 128
#define GSM  211456

__device__ __forceinline__ float sigf(float v)   { return __fdividef(1.0f, 1.0f + __expf(-v)); }
__device__ __forceinline__ float tanhf_(float v) { return 1.0f - __fdividef(2.0f, __expf(2.0f * v) + 1.0f); }

__device__ __forceinline__ void fill_h(uint32_t sb, uint32_t ab,
                                       const __nv_bfloat16* hhi, const __nv_bfloat16* hlo,
                                       int kc, int tid) {
    #pragma unroll
    for (int i = 0; i < 4; i++) {
        int u = tid + i * 256;
        int b = u >> 4, un = u & 15;
        size_t g = (size_t)b * Hz + kc * 128 + un * 8;
        uint32_t d = SWZ(((un >> 3) * 64 + b) * 128 + (un & 7) * 16);
        CP16(sb + ab + d,         hhi + g);
        CP16(sb + ab + 16384 + d, hlo + g);
    }
}

__global__ __launch_bounds__(256, 1) void gru(
    const float* __restrict__ Whr, const float* __restrict__ Whi, const float* __restrict__ Whn,
    float* __restrict__ out, int write_last)
{
    extern __shared__ __align__(16) char sm[];
    uint32_t sb = s2u(sm);
    float* Sacc = (float*)(sm + 196608);      // [2][64][25]
    float* hown = (float*)(sm + 209408);
    int tid = threadIdx.x, lane = tid & 31, wid = tid >> 5;
    int kh = wid & 1, mt = wid >> 1;          // 8 warps = 4 M-tiles x 2 K-halves
    int c = blockIdx.x;

    // one-time resident W (32 n-rows: 24 real + 8 zero) x 1024 k, hi/lo
    #pragma unroll
    for (int i = 0; i < 16; i++) {
        int u = tid + i * 256;
        int n = u >> 7, un = u & 127;
        int k = un * 8;
        uint4 hi = make_uint4(0, 0, 0, 0), lo = hi;
        if (n < 24) {
            const float* W = (n < 8) ? Whr : (n < 16) ? Whi : Whn;
            const float* s = W + (size_t)(c * 8 + (n & 7)) * Hz + k;
            float4 a = *(const float4*)s, b = *(const float4*)(s + 4);
            cvt8(a, b, hi, lo);
        }
        uint32_t off = SWZ(((k >> 6) * 32 + n) * 128 + ((k >> 3) & 7) * 16);
        *(uint4*)(sm + off)         = hi;
        *(uint4*)(sm + 65536 + off) = lo;
    }
    if (tid < 64) {
        #pragma unroll
        for (int j = 0; j < 8; j++) hown[tid * 8 + j] = 0.0f;
    }
    __syncthreads();

    for (int t = 0; t < Tz; t++) {
        int par = t & 1, nxt = par ^ 1;
        const __nv_bfloat16* hhi = g_hhi[par];
        const __nv_bfloat16* hlo = g_hlo[par];

        fill_h(sb, 131072, hhi, hlo, 0, tid);
        CPCOMMIT();

        float xr[8], xi[8], xn[8];
        if (tid < 64) {
            const float* xgrow = g_xg + (size_t)(tid * Tz + t) * G3z + c * 8;
            *(float4*)(xr)     = *(const float4*)(xgrow);
            *(float4*)(xr + 4) = *(const float4*)(xgrow + 4);
            *(float4*)(xi)     = *(const float4*)(xgrow + 1024);
            *(float4*)(xi + 4) = *(const float4*)(xgrow + 1028);
            *(float4*)(xn)     = *(const float4*)(xgrow + 2048);
            *(float4*)(xn + 4) = *(const float4*)(xgrow + 2052);
        }

        float acc[3][4];
        #pragma unroll
        for (int i = 0; i < 3; i++)
            #pragma unroll
            for (int j = 0; j < 4; j++) acc[i][j] = 0.0f;

        for (int kc = 0; kc < 8; kc++) {
            CPWAIT0();
            __syncthreads();
            if (kc < 7)
                fill_h(sb, 131072 + ((kc + 1) & 1) * 32768, hhi, hlo, kc + 1, tid);
            CPCOMMIT();
            uint32_t ab = 131072 + (kc & 1) * 32768;

            #pragma unroll
            for (int ks = 0; ks < 4; ks++) {
                // A fragment: loaded once, reused for all 3 N-slices x 3 passes
                uint32_t ah[4], al[4];
                int kk  = kh * 64 + ks * 16;
                int akk = kk + (lane >> 4) * 8;
                int arow = mt * 16 + (lane & 7) + (lane & 8);
                uint32_t o = SWZ(((akk >> 6) * 64 + arow) * 128 + ((akk >> 3) & 7) * 16);
                LDSM4(ah, sb + ab + o);
                LDSM4(al, sb + ab + 16384 + o);
                int bkk = kc * 128 + kk + ((lane >> 3) & 1) * 8;
                #pragma unroll
                for (int wn = 0; wn < 3; wn++) {
                    uint32_t bh[2], bl[2];
                    int brow = wn * 8 + (lane & 7);
                    uint32_t ob = SWZ(((bkk >> 6) * 32 + brow) * 128 + ((bkk >> 3) & 7) * 16);
                    LDSM2(bh, sb + ob);
                    LDSM2(bl, sb + 65536 + ob);
                    MMA(acc[wn], ah, bh);
                    MMA(acc[wn], ah, bl);
                    MMA(acc[wn], al, bh);
                }
            }
        }

        // store partial gate pre-activations (each slot written once per K-half)
        {
            float* S = Sacc + kh * 1600;
            int row = mt * 16 + (lane >> 2);
            #pragma unroll
            for (int wn = 0; wn < 3; wn++) {
                int col = wn * 8 + 2 * (lane & 3);
                S[row * 25 + col]           = acc[wn][0];
                S[row * 25 + col + 1]       = acc[wn][1];
                S[(row + 8) * 25 + col]     = acc[wn][2];
                S[(row + 8) * 25 + col + 1] = acc[wn][3];
            }
        }
        __syncthreads();

        if (tid < 64) {
            int b = tid;
            const float* S0 = Sacc + b * 25;
            const float* S1 = Sacc + 1600 + b * 25;
            float hn[8];
            #pragma unroll
            for (int j = 0; j < 8; j++) {
                float r  = sigf(xr[j] + S0[j] + S1[j]);
                float z  = sigf(xi[j] + S0[8 + j] + S1[8 + j]);
                float nn = tanhf_(xn[j] + r * (S0[16 + j] + S1[16 + j]));
                hn[j] = (1.0f - z) * nn + z * hown[b * 8 + j];
                hown[b * 8 + j] = hn[j];
            }
            float4 o0 = make_float4(hn[0], hn[1], hn[2], hn[3]);
            float4 o1 = make_float4(hn[4], hn[5], hn[6], hn[7]);
            float* orow = out + (size_t)(b * Tz + t) * Hz + c * 8;
            *(float4*)orow = o0;
            *(float4*)(orow + 4) = o1;
            if (write_last && t == Tz - 1) {
                float* lrow = out + (size_t)BTz * Hz + (size_t)b * Hz + c * 8;
                *(float4*)lrow = o0;
                *(float4*)(lrow + 4) = o1;
            }
            uint4 hi, lo;
            cvt8(o0, o1, hi, lo);
            __stcg((uint4*)(g_hhi[nxt] + (size_t)b * Hz + c * 8), hi);
            __stcg((uint4*)(g_hlo[nxt] + (size_t)b * Hz + c * 8), lo);
        }
        grid_sync_t(t, c);
    }
}

// ---------------- launch ----------------
extern "C" void kernel_launch(void* const* d_in, const int* in_sizes, int n_in,
                              void* d_out, int out_size) {
    const float* x   = (const float*)d_in[0];
    const float* Wir = (const float*)d_in[1];
    const float* Wii = (const float*)d_in[2];
    const float* Win = (const float*)d_in[3];
    const float* bir = (const float*)d_in[4];
    const float* bii = (const float*)d_in[5];
    const float* bin = (const float*)d_in[6];
    const float* Whr = (const float*)d_in[7];
    const float* Whi = (const float*)d_in[8];
    const float* Whn = (const float*)d_in[9];
    float* out = (float*)d_out;

    int write_last = (out_size >= BTz * Hz + Bz * Hz) ? 1 : 0;

    cudaFuncSetAttribute(xproj, cudaFuncAttributeMaxDynamicSharedMemorySize, XSM);
    cudaFuncSetAttribute(gru,   cudaFuncAttributeMaxDynamicSharedMemorySize, GSM);

    init_h<<<(Bz * Hz + 255) / 256, 256>>>();
    cvt_x<<<(int)(((size_t)BTz * INz / 8 + 255) / 256), 256>>>(x);
    cvt_w<<<(G3z * INz / 8 + 255) / 256, 256>>>(Wir, Wii, Win, bir, bii, bin);

    dim3 g1(BTz / 128, G3z / 64);
    xproj<<<g1, 256, XSM>>>();

    gru<<<NCTA, 256, GSM>>>(Whr, Whi, Whn, out, write_last);
}